// round 9
// baseline (speedup 1.0000x reference)
#include <cuda_runtime.h>

#define H 16
#define T 2048
#define D 1024
#define DH 64
#define N3 3072
#define PI 128

// ---------------- scratch (no allocations allowed) ----------------
__device__ float g_q[H*T*DH];
__device__ float g_k[H*T*DH];
__device__ float g_v[H*T*DH];
__device__ float g_ao[H*T*DH];
__device__ int   g_cum[T];
__device__ float g_ns[32][H*DH*DH];   // newstate partials per chunk-group

// ---------------- packed f32x2 helpers ----------------
__device__ __forceinline__ void ffma2(unsigned long long& d, unsigned long long a, unsigned long long b) {
    asm("fma.rn.f32x2 %0, %1, %2, %0;" : "+l"(d) : "l"(a), "l"(b));
}
__device__ __forceinline__ void upk(unsigned long long v, float& lo, float& hi) {
    asm("mov.b64 {%0,%1}, %2;" : "=f"(lo), "=f"(hi) : "l"(v));
}

// ---------------- cumsum of done (dtype auto-detect) ----------------
__global__ void cumsum_kernel(const unsigned char* __restrict__ done) {
    __shared__ int tsum[256];
    __shared__ int s_big, s_off4;
    int tid = threadIdx.x;
    if (tid == 0) { s_big = 0; s_off4 = 0; }
    __syncthreads();
    int big = 0, off4 = 0;
    for (int i = tid; i < 2048; i += 256) {
        unsigned char bb = done[i];
        if (bb > 1) big = 1;
        if (bb != 0 && (i & 3) != 0) off4 = 1;
    }
    if (big)  atomicOr(&s_big, 1);
    if (off4) atomicOr(&s_off4, 1);
    __syncthreads();
    int mode = s_big ? 2 : (s_off4 ? 0 : 1);  // 0=bool, 1=int32, 2=float32

    int loc[8]; int s = 0;
#pragma unroll
    for (int i = 0; i < 8; i++) {
        int t = tid*8 + i;
        int v;
        if (mode == 0)      v = (done[t] != 0);
        else if (mode == 1) v = (((const int*)done)[t] != 0);
        else                v = (((const float*)done)[t] != 0.0f);
        loc[i] = v; s += v;
    }
    tsum[tid] = s; __syncthreads();
    for (int off = 1; off < 256; off <<= 1) {
        int v = (tid >= off) ? tsum[tid - off] : 0;
        __syncthreads();
        tsum[tid] += v;
        __syncthreads();
    }
    int run = (tid > 0) ? tsum[tid-1] : 0;
#pragma unroll
    for (int i = 0; i < 8; i++) { run += loc[i]; g_cum[tid*8 + i] = run; }
}

// ---------------- qkv GEMM: x(2048x1024) @ w(1024x3072) + b ----------------
// 64x64 tile, 256 threads, thread tile 4x4. FFMA2 inner loop:
// A pairs come straight from transposed As; B pairs are duplicated in Bs.
__global__ void qkv_gemm_kernel(const float* __restrict__ x,
                                const float* __restrict__ w,
                                const float* __restrict__ b) {
    __shared__ float As[16][68];    // [k][m], 272B rows -> 16B aligned at m%4==0
    __shared__ float Bs[16][128];   // [k][2n], duplicated pairs
    int bm = blockIdx.y, bn = blockIdx.x;
    int tid = threadIdx.x;
    int tx = tid & 15, ty = tid >> 4;
    unsigned long long acc[2][4] = {};   // [m-pair][n]
    int arow = tid >> 2, akk = (tid & 3) * 4;
    int bkk = tid >> 4, bn4 = (tid & 15) * 4;
    const float* xp = x + (bm*64 + arow)*D + akk;
    const float* wp = w + bkk*N3 + bn*64 + bn4;
    for (int kt = 0; kt < D/16; kt++) {
        float4 a = *(const float4*)(xp + kt*16);
        As[akk+0][arow] = a.x; As[akk+1][arow] = a.y;
        As[akk+2][arow] = a.z; As[akk+3][arow] = a.w;
        float4 bv = *(const float4*)(wp + kt*16*N3);
        *(float4*)&Bs[bkk][bn4*2]     = make_float4(bv.x, bv.x, bv.y, bv.y);
        *(float4*)&Bs[bkk][bn4*2 + 4] = make_float4(bv.z, bv.z, bv.w, bv.w);
        __syncthreads();
#pragma unroll
        for (int kk = 0; kk < 16; kk++) {
            ulonglong2 ap = *(const ulonglong2*)&As[kk][ty*4];
            ulonglong2 b0 = *(const ulonglong2*)&Bs[kk][tx*8];
            ulonglong2 b1 = *(const ulonglong2*)&Bs[kk][tx*8 + 4];
            ffma2(acc[0][0], ap.x, b0.x); ffma2(acc[1][0], ap.y, b0.x);
            ffma2(acc[0][1], ap.x, b0.y); ffma2(acc[1][1], ap.y, b0.y);
            ffma2(acc[0][2], ap.x, b1.x); ffma2(acc[1][2], ap.y, b1.x);
            ffma2(acc[0][3], ap.x, b1.y); ffma2(acc[1][3], ap.y, b1.y);
        }
        __syncthreads();
    }
#pragma unroll
    for (int p = 0; p < 2; p++) {
        int m0 = bm*64 + ty*4 + p*2;
#pragma unroll
        for (int j = 0; j < 4; j++) {
            int n = bn*64 + tx*4 + j;
            float lo, hi; upk(acc[p][j], lo, hi);
            float bias = b[n];
            int qkv = n >> 10;
            int h   = (n >> 6) & 15;
            int dh  = n & 63;
            float* dst = (qkv == 0) ? g_q : ((qkv == 1) ? g_k : g_v);
            dst[(h*T + m0    )*DH + dh] = lo + bias;
            dst[(h*T + m0 + 1)*DH + dh] = hi + bias;
        }
    }
}

// ---------------- out projection: ao(T x D, head-chunked) @ w_out + b_out ----------------
__global__ void out_gemm_kernel(const float* __restrict__ w,
                                const float* __restrict__ b,
                                float* __restrict__ xout) {
    __shared__ float As[16][68];
    __shared__ float Bs[16][128];
    int bm = blockIdx.y, bn = blockIdx.x;
    int tid = threadIdx.x;
    int tx = tid & 15, ty = tid >> 4;
    unsigned long long acc[2][4] = {};
    int arow = tid >> 2, akk = (tid & 3) * 4;
    int bkk = tid >> 4, bn4 = (tid & 15) * 4;
    int m = bm*64 + arow;
    for (int kt = 0; kt < D/16; kt++) {
        int k  = kt*16 + akk;
        int hh = k >> 6, dh = k & 63;
        float4 a = *(const float4*)(g_ao + (hh*T + m)*DH + dh);
        As[akk+0][arow] = a.x; As[akk+1][arow] = a.y;
        As[akk+2][arow] = a.z; As[akk+3][arow] = a.w;
        float4 bv = *(const float4*)(w + (kt*16 + bkk)*D + bn*64 + bn4);
        *(float4*)&Bs[bkk][bn4*2]     = make_float4(bv.x, bv.x, bv.y, bv.y);
        *(float4*)&Bs[bkk][bn4*2 + 4] = make_float4(bv.z, bv.z, bv.w, bv.w);
        __syncthreads();
#pragma unroll
        for (int kk = 0; kk < 16; kk++) {
            ulonglong2 ap = *(const ulonglong2*)&As[kk][ty*4];
            ulonglong2 b0 = *(const ulonglong2*)&Bs[kk][tx*8];
            ulonglong2 b1 = *(const ulonglong2*)&Bs[kk][tx*8 + 4];
            ffma2(acc[0][0], ap.x, b0.x); ffma2(acc[1][0], ap.y, b0.x);
            ffma2(acc[0][1], ap.x, b0.y); ffma2(acc[1][1], ap.y, b0.y);
            ffma2(acc[0][2], ap.x, b1.x); ffma2(acc[1][2], ap.y, b1.x);
            ffma2(acc[0][3], ap.x, b1.y); ffma2(acc[1][3], ap.y, b1.y);
        }
        __syncthreads();
    }
#pragma unroll
    for (int p = 0; p < 2; p++) {
        int m0 = bm*64 + ty*4 + p*2;
#pragma unroll
        for (int j = 0; j < 4; j++) {
            int n = bn*64 + tx*4 + j;
            float lo, hi; upk(acc[p][j], lo, hi);
            float bias = b[n];
            xout[(m0    )*D + n] = lo + bias;
            xout[(m0 + 1)*D + n] = hi + bias;
        }
    }
}

// ---------------- attention (unchanged, known-good) ----------------
__global__ void attn_kernel(const float* __restrict__ state) {
    extern __shared__ float sm[];
    float* qs = sm;                   // [64][PI]  q transposed: qs[d][i]
    float* ks = qs + 64*PI;           // [64][68]  k transposed: ks[d][j] (also state)
    float* vs = ks + 64*68;           // [64][64]  vs[j][d]
    float* Ss = vs + 64*64;           // [64][PI]  S transposed: Ss[j][i]
    int*   cq = (int*)(Ss + 64*PI);   // [128]
    int*   ck = cq + 128;             // [64]

    int h  = blockIdx.y;
    int tb = blockIdx.x;
    int t0 = tb * 128;
    int tid = threadIdx.x;
    int tx = tid & 15, ty = tid >> 4;

    const float* qg = g_q + (h*T + t0)*DH;
#pragma unroll
    for (int r = 0; r < 8; r++) {
        int idx = tid + r*256;
        int i = idx >> 4, c4 = (idx & 15) * 4;
        float4 a = *(const float4*)(qg + i*DH + c4);
        qs[(c4+0)*PI + i] = a.x;
        qs[(c4+1)*PI + i] = a.y;
        qs[(c4+2)*PI + i] = a.z;
        qs[(c4+3)*PI + i] = a.w;
    }
    if (tid < 128) cq[tid] = g_cum[t0 + tid];
    __syncthreads();

    float acc[8][4] = {};
    int cum_t0 = cq[0];

    int sb_max = 2*tb + 1;
    for (int sb = 0; sb <= sb_max; sb++) {
        int s0 = sb * 64;
        if (g_cum[s0 + 63] < cum_t0) continue;

        const float* kg = g_k + (h*T + s0)*DH;
        const float* vg = g_v + (h*T + s0)*DH;
#pragma unroll
        for (int r = 0; r < 4; r++) {
            int idx = tid + r*256;
            int j = idx >> 4, c4 = (idx & 15) * 4;
            float4 a = *(const float4*)(kg + j*DH + c4);
            ks[(c4+0)*68 + j] = a.x;
            ks[(c4+1)*68 + j] = a.y;
            ks[(c4+2)*68 + j] = a.z;
            ks[(c4+3)*68 + j] = a.w;
            *(float4*)&vs[j*64 + c4] = *(const float4*)(vg + j*DH + c4);
        }
        if (tid < 64) ck[tid] = g_cum[s0 + tid];
        __syncthreads();

        float sacc[8][4] = {};
#pragma unroll 8
        for (int d = 0; d < 64; d++) {
            float4 a0 = *(const float4*)&qs[d*PI + ty*8];
            float4 a1 = *(const float4*)&qs[d*PI + ty*8 + 4];
            float4 bv = *(const float4*)&ks[d*68 + tx*4];
            float aa[8] = {a0.x,a0.y,a0.z,a0.w,a1.x,a1.y,a1.z,a1.w};
            float bb[4] = {bv.x,bv.y,bv.z,bv.w};
#pragma unroll
            for (int i = 0; i < 8; i++)
#pragma unroll
                for (int j = 0; j < 4; j++) sacc[i][j] += aa[i] * bb[j];
        }
#pragma unroll
        for (int j = 0; j < 4; j++) {
            int s  = s0 + tx*4 + j;
            int cs = ck[tx*4 + j];
            float tmp[8];
#pragma unroll
            for (int i = 0; i < 8; i++) {
                int t = t0 + ty*8 + i;
                bool m = (s <= t) && (cs == cq[ty*8 + i]);
                tmp[i] = m ? sacc[i][j] : 0.0f;
            }
            *(float4*)&Ss[(tx*4+j)*PI + ty*8]     = make_float4(tmp[0],tmp[1],tmp[2],tmp[3]);
            *(float4*)&Ss[(tx*4+j)*PI + ty*8 + 4] = make_float4(tmp[4],tmp[5],tmp[6],tmp[7]);
        }
        __syncthreads();

#pragma unroll 8
        for (int s = 0; s < 64; s++) {
            float4 a0 = *(const float4*)&Ss[s*PI + ty*8];
            float4 a1 = *(const float4*)&Ss[s*PI + ty*8 + 4];
            float4 bv = *(const float4*)&vs[s*64 + tx*4];
            float aa[8] = {a0.x,a0.y,a0.z,a0.w,a1.x,a1.y,a1.z,a1.w};
            float bb[4] = {bv.x,bv.y,bv.z,bv.w};
#pragma unroll
            for (int i = 0; i < 8; i++)
#pragma unroll
                for (int j = 0; j < 4; j++) acc[i][j] += aa[i] * bb[j];
        }
        __syncthreads();
    }

    if (cum_t0 == 0) {
#pragma unroll
        for (int r = 0; r < 4; r++) {
            int idx = tid + r*256;
            int e = idx >> 4, c4 = (idx & 15) * 4;
            *(float4*)&ks[e*68 + c4] = *(const float4*)(state + (h*64 + e)*64 + c4);
        }
        __syncthreads();
        float sacc[8][4] = {};
#pragma unroll 8
        for (int e = 0; e < 64; e++) {
            float4 a0 = *(const float4*)&qs[e*PI + ty*8];
            float4 a1 = *(const float4*)&qs[e*PI + ty*8 + 4];
            float4 bv = *(const float4*)&ks[e*68 + tx*4];
            float aa[8] = {a0.x,a0.y,a0.z,a0.w,a1.x,a1.y,a1.z,a1.w};
            float bb[4] = {bv.x,bv.y,bv.z,bv.w};
#pragma unroll
            for (int i = 0; i < 8; i++)
#pragma unroll
                for (int j = 0; j < 4; j++) sacc[i][j] += aa[i] * bb[j];
        }
#pragma unroll
        for (int i = 0; i < 8; i++) {
            if (cq[ty*8 + i] == 0) {
#pragma unroll
                for (int j = 0; j < 4; j++) acc[i][j] += sacc[i][j];
            }
        }
    }

    float* og = g_ao + (h*T + t0)*DH;
#pragma unroll
    for (int i = 0; i < 8; i++) {
        *(float4*)&og[(ty*8+i)*DH + tx*4] = make_float4(acc[i][0],acc[i][1],acc[i][2],acc[i][3]);
    }
}

// ---------------- new_state: parallel partials + deterministic reduce ----------------
// grid (32, H): chunk c covers tokens [c*64, c*64+64).
__global__ void newstate_partial_kernel() {
    __shared__ float kt[64][68];
    __shared__ float vt[64][64];
    int c = blockIdx.x;
    int h = blockIdx.y;
    int tid = threadIdx.x;
    int d = tid >> 2;
    int eg = (tid & 3) * 16;
    int cum_last = g_cum[T-1];
    int t0 = c*64;
    float* dst = &g_ns[c][h*4096 + d*64 + eg];
    if (g_cum[t0 + 63] < cum_last) {   // entirely before after_last suffix
#pragma unroll
        for (int e = 0; e < 16; e++) dst[e] = 0.0f;
        return;
    }
    float acc[16] = {};
#pragma unroll
    for (int r = 0; r < 4; r++) {
        int idx = tid + r*256;
        int tt = idx >> 4, c4 = (idx & 15) * 4;
        int t = t0 + tt;
        float m = (g_cum[t] == cum_last) ? 1.0f : 0.0f;
        float4 a = *(const float4*)(g_k + (h*T + t)*DH + c4);
        kt[tt][c4+0] = a.x*m; kt[tt][c4+1] = a.y*m;
        kt[tt][c4+2] = a.z*m; kt[tt][c4+3] = a.w*m;
        *(float4*)&vt[tt][c4] = *(const float4*)(g_v + (h*T + t)*DH + c4);
    }
    __syncthreads();
    for (int tt = 0; tt < 64; tt++) {
        float kv = kt[tt][d];
#pragma unroll
        for (int e4 = 0; e4 < 4; e4++) {
            float4 v4 = *(const float4*)&vt[tt][eg + e4*4];
            acc[e4*4+0] += kv * v4.x;
            acc[e4*4+1] += kv * v4.y;
            acc[e4*4+2] += kv * v4.z;
            acc[e4*4+3] += kv * v4.w;
        }
    }
#pragma unroll
    for (int e = 0; e < 16; e++) dst[e] = acc[e];
}

__global__ void newstate_reduce_kernel(const float* __restrict__ state,
                                       float* __restrict__ out) {
    int i = blockIdx.x * blockDim.x + threadIdx.x;  // 65536 total
    bool done_any = g_cum[T-1] > 0;
    float s = done_any ? 0.0f : state[i];
#pragma unroll
    for (int c = 0; c < 32; c++) s += g_ns[c][i];
    out[i] = s;
}

// ---------------- launch ----------------
static const int ATTN_SMEM = (64*PI + 64*68 + 64*64 + 64*PI) * 4 + (128 + 64) * 4;

extern "C" void kernel_launch(void* const* d_in, const int* in_sizes, int n_in,
                              void* d_out, int out_size) {
    const float* state  = (const float*)d_in[0];
    const float* x      = (const float*)d_in[1];
    const unsigned char* done = (const unsigned char*)d_in[2];
    const float* w_qkv  = (const float*)d_in[3];
    const float* b_qkv  = (const float*)d_in[4];
    const float* w_out  = (const float*)d_in[5];
    const float* b_out  = (const float*)d_in[6];

    float* out_state = (float*)d_out;            // H*DH*DH = 65536 elems
    float* out_x     = out_state + H*DH*DH;      // T*D elems

    cudaFuncSetAttribute(attn_kernel, cudaFuncAttributeMaxDynamicSharedMemorySize, ATTN_SMEM);

    cumsum_kernel<<<1, 256>>>(done);
    qkv_gemm_kernel<<<dim3(N3/64, T/64), 256>>>(x, w_qkv, b_qkv);
    attn_kernel<<<dim3(T/128, H), 256, ATTN_SMEM>>>(state);
    newstate_partial_kernel<<<dim3(32, H), 256>>>();
    newstate_reduce_kernel<<<64, 1024>>>(state, out_state);
    out_gemm_kernel<<<dim3(D/64, T/64), 256>>>(w_out, b_out, out_x);
}

// round 10
// speedup vs baseline: 1.9884x; 1.9884x over previous
#include <cuda_runtime.h>

#define H 16
#define T 2048
#define D 1024
#define DH 64
#define N3 3072
#define PI 128

// ---------------- scratch (no allocations allowed) ----------------
__device__ float g_q[H*T*DH];
__device__ float g_k[H*T*DH];
__device__ float g_v[H*T*DH];
__device__ float g_ao[H*T*DH];
__device__ int   g_cum[T];
__device__ float g_ns[32][H*DH*DH];   // newstate partials per chunk

// ---------------- cumsum of done (dtype auto-detect) ----------------
__global__ void cumsum_kernel(const unsigned char* __restrict__ done) {
    __shared__ int tsum[256];
    __shared__ int s_big, s_off4;
    int tid = threadIdx.x;
    if (tid == 0) { s_big = 0; s_off4 = 0; }
    __syncthreads();
    int big = 0, off4 = 0;
    for (int i = tid; i < 2048; i += 256) {
        unsigned char bb = done[i];
        if (bb > 1) big = 1;
        if (bb != 0 && (i & 3) != 0) off4 = 1;
    }
    if (big)  atomicOr(&s_big, 1);
    if (off4) atomicOr(&s_off4, 1);
    __syncthreads();
    int mode = s_big ? 2 : (s_off4 ? 0 : 1);  // 0=bool, 1=int32, 2=float32

    int loc[8]; int s = 0;
#pragma unroll
    for (int i = 0; i < 8; i++) {
        int t = tid*8 + i;
        int v;
        if (mode == 0)      v = (done[t] != 0);
        else if (mode == 1) v = (((const int*)done)[t] != 0);
        else                v = (((const float*)done)[t] != 0.0f);
        loc[i] = v; s += v;
    }
    tsum[tid] = s; __syncthreads();
    for (int off = 1; off < 256; off <<= 1) {
        int v = (tid >= off) ? tsum[tid - off] : 0;
        __syncthreads();
        tsum[tid] += v;
        __syncthreads();
    }
    int run = (tid > 0) ? tsum[tid-1] : 0;
#pragma unroll
    for (int i = 0; i < 8; i++) { run += loc[i]; g_cum[tid*8 + i] = run; }
}

// ---------------- qkv GEMM: x(2048x1024) @ w(1024x3072) + b ----------------
// epilogue scatters to g_q/g_k/g_v in (H, T, DH) layout  (round-6 known-good)
__global__ void qkv_gemm_kernel(const float* __restrict__ x,
                                const float* __restrict__ w,
                                const float* __restrict__ b) {
    __shared__ float As[16][68];
    __shared__ float Bs[16][64];
    int bm = blockIdx.y, bn = blockIdx.x;
    int tid = threadIdx.x;
    int tx = tid & 15, ty = tid >> 4;
    float acc[4][4] = {};
    int arow = tid >> 2, akk = (tid & 3) * 4;
    int bkk = tid >> 4, bn4 = (tid & 15) * 4;
    const float* xp = x + (bm*64 + arow)*D + akk;
    const float* wp = w + bkk*N3 + bn*64 + bn4;
    for (int kt = 0; kt < D/16; kt++) {
        float4 a = *(const float4*)(xp + kt*16);
        As[akk+0][arow] = a.x; As[akk+1][arow] = a.y;
        As[akk+2][arow] = a.z; As[akk+3][arow] = a.w;
        *(float4*)&Bs[bkk][bn4] = *(const float4*)(wp + kt*16*N3);
        __syncthreads();
#pragma unroll
        for (int kk = 0; kk < 16; kk++) {
            float4 av = *(const float4*)&As[kk][ty*4];
            float4 bv = *(const float4*)&Bs[kk][tx*4];
            float aa[4] = {av.x, av.y, av.z, av.w};
            float bb[4] = {bv.x, bv.y, bv.z, bv.w};
#pragma unroll
            for (int i = 0; i < 4; i++)
#pragma unroll
                for (int j = 0; j < 4; j++) acc[i][j] += aa[i] * bb[j];
        }
        __syncthreads();
    }
#pragma unroll
    for (int i = 0; i < 4; i++) {
        int m = bm*64 + ty*4 + i;
#pragma unroll
        for (int j = 0; j < 4; j++) {
            int n = bn*64 + tx*4 + j;
            float val = acc[i][j] + b[n];
            int qkv = n >> 10;
            int h   = (n >> 6) & 15;
            int dh  = n & 63;
            float* dst = (qkv == 0) ? g_q : ((qkv == 1) ? g_k : g_v);
            dst[(h*T + m)*DH + dh] = val;
        }
    }
}

// ---------------- attention (round-6 known-good) ----------------
__global__ void attn_kernel(const float* __restrict__ state) {
    extern __shared__ float sm[];
    float* qs = sm;                   // [64][PI]  q transposed: qs[d][i]
    float* ks = qs + 64*PI;           // [64][68]  k transposed: ks[d][j] (also state)
    float* vs = ks + 64*68;           // [64][64]  vs[j][d]
    float* Ss = vs + 64*64;           // [64][PI]  S transposed: Ss[j][i]
    int*   cq = (int*)(Ss + 64*PI);   // [128]
    int*   ck = cq + 128;             // [64]

    int h  = blockIdx.y;
    int tb = blockIdx.x;
    int t0 = tb * 128;
    int tid = threadIdx.x;
    int tx = tid & 15, ty = tid >> 4;

    const float* qg = g_q + (h*T + t0)*DH;
#pragma unroll
    for (int r = 0; r < 8; r++) {
        int idx = tid + r*256;
        int i = idx >> 4, c4 = (idx & 15) * 4;
        float4 a = *(const float4*)(qg + i*DH + c4);
        qs[(c4+0)*PI + i] = a.x;
        qs[(c4+1)*PI + i] = a.y;
        qs[(c4+2)*PI + i] = a.z;
        qs[(c4+3)*PI + i] = a.w;
    }
    if (tid < 128) cq[tid] = g_cum[t0 + tid];
    __syncthreads();

    float acc[8][4] = {};
    int cum_t0 = cq[0];

    int sb_max = 2*tb + 1;
    for (int sb = 0; sb <= sb_max; sb++) {
        int s0 = sb * 64;
        if (g_cum[s0 + 63] < cum_t0) continue;

        const float* kg = g_k + (h*T + s0)*DH;
        const float* vg = g_v + (h*T + s0)*DH;
#pragma unroll
        for (int r = 0; r < 4; r++) {
            int idx = tid + r*256;
            int j = idx >> 4, c4 = (idx & 15) * 4;
            float4 a = *(const float4*)(kg + j*DH + c4);
            ks[(c4+0)*68 + j] = a.x;
            ks[(c4+1)*68 + j] = a.y;
            ks[(c4+2)*68 + j] = a.z;
            ks[(c4+3)*68 + j] = a.w;
            *(float4*)&vs[j*64 + c4] = *(const float4*)(vg + j*DH + c4);
        }
        if (tid < 64) ck[tid] = g_cum[s0 + tid];
        __syncthreads();

        float sacc[8][4] = {};
#pragma unroll 8
        for (int d = 0; d < 64; d++) {
            float4 a0 = *(const float4*)&qs[d*PI + ty*8];
            float4 a1 = *(const float4*)&qs[d*PI + ty*8 + 4];
            float4 bv = *(const float4*)&ks[d*68 + tx*4];
            float aa[8] = {a0.x,a0.y,a0.z,a0.w,a1.x,a1.y,a1.z,a1.w};
            float bb[4] = {bv.x,bv.y,bv.z,bv.w};
#pragma unroll
            for (int i = 0; i < 8; i++)
#pragma unroll
                for (int j = 0; j < 4; j++) sacc[i][j] += aa[i] * bb[j];
        }
#pragma unroll
        for (int j = 0; j < 4; j++) {
            int s  = s0 + tx*4 + j;
            int cs = ck[tx*4 + j];
            float tmp[8];
#pragma unroll
            for (int i = 0; i < 8; i++) {
                int t = t0 + ty*8 + i;
                bool m = (s <= t) && (cs == cq[ty*8 + i]);
                tmp[i] = m ? sacc[i][j] : 0.0f;
            }
            *(float4*)&Ss[(tx*4+j)*PI + ty*8]     = make_float4(tmp[0],tmp[1],tmp[2],tmp[3]);
            *(float4*)&Ss[(tx*4+j)*PI + ty*8 + 4] = make_float4(tmp[4],tmp[5],tmp[6],tmp[7]);
        }
        __syncthreads();

#pragma unroll 8
        for (int s = 0; s < 64; s++) {
            float4 a0 = *(const float4*)&Ss[s*PI + ty*8];
            float4 a1 = *(const float4*)&Ss[s*PI + ty*8 + 4];
            float4 bv = *(const float4*)&vs[s*64 + tx*4];
            float aa[8] = {a0.x,a0.y,a0.z,a0.w,a1.x,a1.y,a1.z,a1.w};
            float bb[4] = {bv.x,bv.y,bv.z,bv.w};
#pragma unroll
            for (int i = 0; i < 8; i++)
#pragma unroll
                for (int j = 0; j < 4; j++) acc[i][j] += aa[i] * bb[j];
        }
        __syncthreads();
    }

    if (cum_t0 == 0) {
#pragma unroll
        for (int r = 0; r < 4; r++) {
            int idx = tid + r*256;
            int e = idx >> 4, c4 = (idx & 15) * 4;
            *(float4*)&ks[e*68 + c4] = *(const float4*)(state + (h*64 + e)*64 + c4);
        }
        __syncthreads();
        float sacc[8][4] = {};
#pragma unroll 8
        for (int e = 0; e < 64; e++) {
            float4 a0 = *(const float4*)&qs[e*PI + ty*8];
            float4 a1 = *(const float4*)&qs[e*PI + ty*8 + 4];
            float4 bv = *(const float4*)&ks[e*68 + tx*4];
            float aa[8] = {a0.x,a0.y,a0.z,a0.w,a1.x,a1.y,a1.z,a1.w};
            float bb[4] = {bv.x,bv.y,bv.z,bv.w};
#pragma unroll
            for (int i = 0; i < 8; i++)
#pragma unroll
                for (int j = 0; j < 4; j++) sacc[i][j] += aa[i] * bb[j];
        }
#pragma unroll
        for (int i = 0; i < 8; i++) {
            if (cq[ty*8 + i] == 0) {
#pragma unroll
                for (int j = 0; j < 4; j++) acc[i][j] += sacc[i][j];
            }
        }
    }

    float* og = g_ao + (h*T + t0)*DH;
#pragma unroll
    for (int i = 0; i < 8; i++) {
        *(float4*)&og[(ty*8+i)*DH + tx*4] = make_float4(acc[i][0],acc[i][1],acc[i][2],acc[i][3]);
    }
}

// ---------------- new_state: parallel partials + deterministic reduce ----------------
// grid (32, H): chunk c covers tokens [c*64, c*64+64).  (round-9 measured-good)
__global__ void newstate_partial_kernel() {
    __shared__ float kt[64][68];
    __shared__ float vt[64][64];
    int c = blockIdx.x;
    int h = blockIdx.y;
    int tid = threadIdx.x;
    int d = tid >> 2;
    int eg = (tid & 3) * 16;
    int cum_last = g_cum[T-1];
    int t0 = c*64;
    float* dst = &g_ns[c][h*4096 + d*64 + eg];
    if (g_cum[t0 + 63] < cum_last) {   // entirely before after_last suffix
#pragma unroll
        for (int e = 0; e < 16; e++) dst[e] = 0.0f;
        return;
    }
    float acc[16] = {};
#pragma unroll
    for (int r = 0; r < 4; r++) {
        int idx = tid + r*256;
        int tt = idx >> 4, c4 = (idx & 15) * 4;
        int t = t0 + tt;
        float m = (g_cum[t] == cum_last) ? 1.0f : 0.0f;
        float4 a = *(const float4*)(g_k + (h*T + t)*DH + c4);
        kt[tt][c4+0] = a.x*m; kt[tt][c4+1] = a.y*m;
        kt[tt][c4+2] = a.z*m; kt[tt][c4+3] = a.w*m;
        *(float4*)&vt[tt][c4] = *(const float4*)(g_v + (h*T + t)*DH + c4);
    }
    __syncthreads();
    for (int tt = 0; tt < 64; tt++) {
        float kv = kt[tt][d];
#pragma unroll
        for (int e4 = 0; e4 < 4; e4++) {
            float4 v4 = *(const float4*)&vt[tt][eg + e4*4];
            acc[e4*4+0] += kv * v4.x;
            acc[e4*4+1] += kv * v4.y;
            acc[e4*4+2] += kv * v4.z;
            acc[e4*4+3] += kv * v4.w;
        }
    }
#pragma unroll
    for (int e = 0; e < 16; e++) dst[e] = acc[e];
}

__global__ void newstate_reduce_kernel(const float* __restrict__ state,
                                       float* __restrict__ out) {
    int i = blockIdx.x * blockDim.x + threadIdx.x;  // 65536 total
    bool done_any = g_cum[T-1] > 0;
    float s = done_any ? 0.0f : state[i];
#pragma unroll
    for (int c = 0; c < 32; c++) s += g_ns[c][i];
    out[i] = s;
}

// ---------------- out projection: ao(T x D, head-chunked) @ w_out + b_out ----------------
// (round-6 known-good)
__global__ void out_gemm_kernel(const float* __restrict__ w,
                                const float* __restrict__ b,
                                float* __restrict__ xout) {
    __shared__ float As[16][68];
    __shared__ float Bs[16][64];
    int bm = blockIdx.y, bn = blockIdx.x;
    int tid = threadIdx.x;
    int tx = tid & 15, ty = tid >> 4;
    float acc[4][4] = {};
    int arow = tid >> 2, akk = (tid & 3) * 4;
    int bkk = tid >> 4, bn4 = (tid & 15) * 4;
    int m = bm*64 + arow;
    for (int kt = 0; kt < D/16; kt++) {
        int k  = kt*16 + akk;
        int hh = k >> 6, dh = k & 63;
        float4 a = *(const float4*)(g_ao + (hh*T + m)*DH + dh);
        As[akk+0][arow] = a.x; As[akk+1][arow] = a.y;
        As[akk+2][arow] = a.z; As[akk+3][arow] = a.w;
        *(float4*)&Bs[bkk][bn4] = *(const float4*)(w + (kt*16 + bkk)*D + bn*64 + bn4);
        __syncthreads();
#pragma unroll
        for (int kk = 0; kk < 16; kk++) {
            float4 av = *(const float4*)&As[kk][ty*4];
            float4 bv = *(const float4*)&Bs[kk][tx*4];
            float aa[4] = {av.x, av.y, av.z, av.w};
            float bb[4] = {bv.x, bv.y, bv.z, bv.w};
#pragma unroll
            for (int i = 0; i < 4; i++)
#pragma unroll
                for (int j = 0; j < 4; j++) acc[i][j] += aa[i] * bb[j];
        }
        __syncthreads();
    }
#pragma unroll
    for (int i = 0; i < 4; i++) {
        int mm = bm*64 + ty*4 + i;
#pragma unroll
        for (int j = 0; j < 4; j++) {
            int n = bn*64 + tx*4 + j;
            xout[mm*D + n] = acc[i][j] + b[n];
        }
    }
}

// ---------------- launch ----------------
static const int ATTN_SMEM = (64*PI + 64*68 + 64*64 + 64*PI) * 4 + (128 + 64) * 4;

extern "C" void kernel_launch(void* const* d_in, const int* in_sizes, int n_in,
                              void* d_out, int out_size) {
    const float* state  = (const float*)d_in[0];
    const float* x      = (const float*)d_in[1];
    const unsigned char* done = (const unsigned char*)d_in[2];
    const float* w_qkv  = (const float*)d_in[3];
    const float* b_qkv  = (const float*)d_in[4];
    const float* w_out  = (const float*)d_in[5];
    const float* b_out  = (const float*)d_in[6];

    float* out_state = (float*)d_out;            // H*DH*DH = 65536 elems
    float* out_x     = out_state + H*DH*DH;      // T*D elems

    cudaFuncSetAttribute(attn_kernel, cudaFuncAttributeMaxDynamicSharedMemorySize, ATTN_SMEM);

    cumsum_kernel<<<1, 256>>>(done);
    qkv_gemm_kernel<<<dim3(N3/64, T/64), 256>>>(x, w_qkv, b_qkv);
    attn_kernel<<<dim3(T/128, H), 256, ATTN_SMEM>>>(state);
    newstate_partial_kernel<<<dim3(32, H), 256>>>();
    newstate_reduce_kernel<<<64, 1024>>>(state, out_state);
    out_gemm_kernel<<<dim3(D/64, T/64), 256>>>(w_out, b_out, out_x);
}